// round 13
// baseline (speedup 1.0000x reference)
#include <cuda_runtime.h>
#include <cuda_fp16.h>
#include <cstdint>

#define MAX_N 50000
#define MAX_E 800000
#define HF    256
#define NH    4
#define NF    64
#define NEG   0.2f

// ---------------- scratch (device globals; no allocations allowed) ----------
__device__ __half g_proj [(size_t)MAX_N * HF];   // fp16 (halves agg gather bytes)
__device__ float  g_skipb[(size_t)MAX_N * HF];
__device__ float  g_ssrc [MAX_N * NH];
__device__ float  g_strg [MAX_N * NH];
__device__ int    g_deg  [MAX_N];
__device__ int    g_rowstart[MAX_N + 1];
__device__ int    g_pos  [MAX_N];
__device__ int    g_csr  [MAX_E];
__device__ __half g_bt[512 * 256];   // [n 0..511][k] = (W | skip_w)^T, fp16

// ---------------- PTX helpers (arch-generic: sm_80-era) ----------------------
__device__ __forceinline__ uint32_t smem_u32(const void* p) {
    uint32_t a;
    asm("{ .reg .u64 t; cvta.to.shared.u64 t, %1; cvt.u32.u64 %0, t; }" : "=r"(a) : "l"(p));
    return a;
}
__device__ __forceinline__ void cp16(uint32_t saddr, const void* g, int srcsize) {
    asm volatile("cp.async.cg.shared.global [%0], [%1], 16, %2;"
                 :: "r"(saddr), "l"(g), "r"(srcsize) : "memory");
}
#define CP_COMMIT() asm volatile("cp.async.commit_group;" ::: "memory")

#define LDSM_X4(d0, d1, d2, d3, addr) \
    asm volatile("ldmatrix.sync.aligned.m8n8.x4.shared.b16 {%0,%1,%2,%3}, [%4];" \
                 : "=r"(d0), "=r"(d1), "=r"(d2), "=r"(d3) : "r"(addr))

__device__ __forceinline__ void mma16816(float* c, const uint32_t* a, const uint32_t* b) {
    asm volatile(
        "mma.sync.aligned.m16n8k16.row.col.f32.f16.f16.f32 "
        "{%0,%1,%2,%3}, {%4,%5,%6,%7}, {%8,%9}, {%0,%1,%2,%3};"
        : "+f"(c[0]), "+f"(c[1]), "+f"(c[2]), "+f"(c[3])
        : "r"(a[0]), "r"(a[1]), "r"(a[2]), "r"(a[3]), "r"(b[0]), "r"(b[1]));
}

// ---------------- weight prep (also zeroes g_deg) -----------------------------
__global__ void prep_bt_kernel(const float* __restrict__ W, const float* __restrict__ skw,
                               int Nn) {
    int i = blockIdx.x * blockDim.x + threadIdx.x;
    if (i < Nn) g_deg[i] = 0;
    if (i < 512 * 256) {
        int n = i >> 8, k = i & 255;
        float v = (n < 256) ? W[k * 256 + n] : skw[k * 256 + (n - 256)];
        g_bt[i] = __float2half_rn(v);
    }
}

// ---------------- HMMA GEMM: C[M,512] = A[M,256] @ BT^T ----------------------
// fp16 2-chain compensation: A = ah + al (fp16 split), B = bh (fp16).
// 64-row CTA tiles, A resident (hi+lo = 67.6 KB) -> 2 CTAs/SM.
// 8 warps x (64m x 16n) per 128-col bn tile; 3-stage cp.async B pipeline.
// Scores fused into bn 0/1 epilogues; proj stored as fp16.
#define AP       264
#define SA_HI    0
#define SA_LO    33792
#define SB_BASE  67584
#define SB_STAGE 10240
#define LDB_PAD  40
#define SC_OFF   98304            // 64 rows x 4 heads x 2 floats = 512 floats
#define GEMM_SMEM (98304 + 2048)  // 100352

__device__ __forceinline__ void load_A_convert(char* smem, const float* __restrict__ x,
                                               int bm, int M, int tid) {
#pragma unroll
    for (int it = 0; it < 8; it++) {
        int id = tid + it * 256;          // 0..2047 : 64 rows x 32 chunks(8 floats)
        int r = id >> 5, c = id & 31;
        int gr = bm * 64 + r;
        float4 v0 = make_float4(0.f, 0.f, 0.f, 0.f), v1 = v0;
        if (gr < M) {
            const float* src = x + (size_t)gr * 256 + c * 8;
            v0 = *(const float4*)src;
            v1 = *(const float4*)(src + 4);
        }
        float f[8] = {v0.x, v0.y, v0.z, v0.w, v1.x, v1.y, v1.z, v1.w};
        __half2 hi2[4], lo2[4];
#pragma unroll
        for (int j = 0; j < 4; j++) {
            __half ha = __float2half_rn(f[2 * j]);
            __half hb = __float2half_rn(f[2 * j + 1]);
            hi2[j] = __half2(ha, hb);
            lo2[j] = __half2(__float2half_rn(f[2 * j]     - __half2float(ha)),
                             __float2half_rn(f[2 * j + 1] - __half2float(hb)));
        }
        uint32_t dst = (uint32_t)(r * AP * 2 + c * 16);
        *(uint4*)(smem + SA_HI + dst) = *(uint4*)hi2;
        *(uint4*)(smem + SA_LO + dst) = *(uint4*)lo2;
    }
}
__device__ __forceinline__ void issue_B(uint32_t sb, int g, int tid) {
    int bn = g >> 3, ks = g & 7;
    uint32_t base = sb + SB_BASE + (uint32_t)(g % 3) * SB_STAGE;
    int row = tid >> 1;
#pragma unroll
    for (int j = 0; j < 2; j++) {
        int chunk = (tid & 1) * 2 + j;               // 0..3
        int gcol  = ks * 32 + chunk * 8;
        int gn    = bn * 128 + row;
        uint32_t dst = (uint32_t)(row * LDB_PAD * 2 + chunk * 16);
        cp16(base + dst, &g_bt[(size_t)gn * 256 + gcol], 16);
    }
}

__global__ __launch_bounds__(256, 2) void gemm_kernel(const float* __restrict__ x,
                                                      const float* __restrict__ a_src,
                                                      const float* __restrict__ a_trg,
                                                      int M)
{
    extern __shared__ __align__(16) char smem[];
    const uint32_t sb = smem_u32(smem);
    float* s_sc = (float*)(smem + SC_OFF);
    const int tid  = threadIdx.x;
    const int wid  = tid >> 5;
    const int lane = tid & 31;
    const int bm   = blockIdx.x;

    const int wn = wid * 16;          // warp n offset within 128-col tile

    float acc[4][2][4];
#pragma unroll
    for (int i = 0; i < 4; i++)
#pragma unroll
        for (int j = 0; j < 2; j++)
#pragma unroll
            for (int q = 0; q < 4; q++) acc[i][j][q] = 0.f;

    const int g8 = lane >> 3;    // ldmatrix address group 0..3
    const int r8 = lane & 7;

    issue_B(sb, 0, tid);
    CP_COMMIT();
    issue_B(sb, 1, tid);
    CP_COMMIT();
    load_A_convert(smem, x, bm, M, tid);
    for (int v = tid; v < 512; v += 256) s_sc[v] = 0.f;

#pragma unroll 1
    for (int g = 0; g < 32; g++) {
        if (g + 2 < 32) {
            issue_B(sb, g + 2, tid);
            CP_COMMIT();
            asm volatile("cp.async.wait_group 2;" ::: "memory");
        } else if (g + 1 < 32) {
            asm volatile("cp.async.wait_group 1;" ::: "memory");
        } else {
            asm volatile("cp.async.wait_group 0;" ::: "memory");
        }
        __syncthreads();

        const int bn = g >> 3, ks = g & 7;
        const uint32_t stB = sb + SB_BASE + (uint32_t)(g % 3) * SB_STAGE;
#pragma unroll
        for (int k16 = 0; k16 < 32; k16 += 16) {
            uint32_t ah[4][4], al[4][4], bh[2][2];
            // A frags (rows 0..63 shared by all warps)
            {
                int arow = (g8 & 1) * 8 + r8;
                int acol = ks * 32 + k16 + (g8 >> 1) * 8;
                uint32_t aoff = (uint32_t)(arow * AP + acol) * 2;
#pragma unroll
                for (int mi = 0; mi < 4; mi++) {
                    uint32_t ad = sb + aoff + (uint32_t)(mi * 16 * AP * 2);
                    LDSM_X4(ah[mi][0], ah[mi][1], ah[mi][2], ah[mi][3], ad + SA_HI);
                    LDSM_X4(al[mi][0], al[mi][1], al[mi][2], al[mi][3], ad + SA_LO);
                }
            }
            // B frag: this warp's 16 cols
            {
                int brow = wn + (g8 >> 1) * 8 + r8;
                int bcol = k16 + (g8 & 1) * 8;
                uint32_t bd = stB + (uint32_t)(brow * LDB_PAD + bcol) * 2;
                LDSM_X4(bh[0][0], bh[0][1], bh[1][0], bh[1][1], bd);
            }
#pragma unroll
            for (int mi = 0; mi < 4; mi++)
#pragma unroll
                for (int ni = 0; ni < 2; ni++) {
                    mma16816(acc[mi][ni], ah[mi], bh[ni]);
                    mma16816(acc[mi][ni], al[mi], bh[ni]);
                }
        }
        __syncthreads();

        if (ks == 7) {
            const int colbase = (bn & 1) * 128 + wn;   // col within 256-wide half

            if (bn < 2) {
                // fused scores: this warp's cols all in head h
                const int h = colbase >> 6;
#pragma unroll
                for (int mi = 0; mi < 4; mi++) {
                    int rl = mi * 16 + (lane >> 2);
                    float s0 = 0.f, t0 = 0.f, s1 = 0.f, t1 = 0.f;
#pragma unroll
                    for (int ni = 0; ni < 2; ni++) {
                        int gc = colbase + ni * 8 + (lane & 3) * 2;
                        float as0 = a_src[gc], as1 = a_src[gc + 1];
                        float at0 = a_trg[gc], at1 = a_trg[gc + 1];
                        s0 += acc[mi][ni][0] * as0 + acc[mi][ni][1] * as1;
                        t0 += acc[mi][ni][0] * at0 + acc[mi][ni][1] * at1;
                        s1 += acc[mi][ni][2] * as0 + acc[mi][ni][3] * as1;
                        t1 += acc[mi][ni][2] * at0 + acc[mi][ni][3] * at1;
                    }
                    atomicAdd(&s_sc[rl * 8 + h * 2 + 0], s0);
                    atomicAdd(&s_sc[rl * 8 + h * 2 + 1], t0);
                    atomicAdd(&s_sc[(rl + 8) * 8 + h * 2 + 0], s1);
                    atomicAdd(&s_sc[(rl + 8) * 8 + h * 2 + 1], t1);
                }
                // proj stored as fp16
#pragma unroll
                for (int mi = 0; mi < 4; mi++) {
                    int gr = bm * 64 + mi * 16 + (lane >> 2);
#pragma unroll
                    for (int ni = 0; ni < 2; ni++) {
                        int gc = colbase + ni * 8 + (lane & 3) * 2;
                        if (gr < M)
                            *(__half2*)&g_proj[(size_t)gr * 256 + gc] =
                                __floats2half2_rn(acc[mi][ni][0], acc[mi][ni][1]);
                        if (gr + 8 < M)
                            *(__half2*)&g_proj[(size_t)(gr + 8) * 256 + gc] =
                                __floats2half2_rn(acc[mi][ni][2], acc[mi][ni][3]);
                        acc[mi][ni][0] = acc[mi][ni][1] = acc[mi][ni][2] = acc[mi][ni][3] = 0.f;
                    }
                }
            } else {
#pragma unroll
                for (int mi = 0; mi < 4; mi++) {
                    int gr = bm * 64 + mi * 16 + (lane >> 2);
#pragma unroll
                    for (int ni = 0; ni < 2; ni++) {
                        int gc = colbase + ni * 8 + (lane & 3) * 2;
                        if (gr < M)
                            *(float2*)&g_skipb[(size_t)gr * 256 + gc] =
                                make_float2(acc[mi][ni][0], acc[mi][ni][1]);
                        if (gr + 8 < M)
                            *(float2*)&g_skipb[(size_t)(gr + 8) * 256 + gc] =
                                make_float2(acc[mi][ni][2], acc[mi][ni][3]);
                        acc[mi][ni][0] = acc[mi][ni][1] = acc[mi][ni][2] = acc[mi][ni][3] = 0.f;
                    }
                }
            }

            if (bn == 1) {
                __syncthreads();                 // all score atomics done
                if (tid < 256) {
                    int r = tid >> 2, hh = tid & 3;
                    int gr2 = bm * 64 + r;
                    if (gr2 < M) {
                        g_ssrc[gr2 * NH + hh] = s_sc[r * 8 + hh * 2];
                        g_strg[gr2 * NH + hh] = s_sc[r * 8 + hh * 2 + 1];
                    }
                }
            }
        }
    }
}

// ---------------- CSR construction ------------------------------------------
__global__ void hist_kernel(const int* __restrict__ etrg, int E)
{
    int e = blockIdx.x * blockDim.x + threadIdx.x;
    if (e < E) atomicAdd(&g_deg[etrg[e]], 1);
}
__global__ void scan_kernel(int Nn)
{
    __shared__ int warpsum[32];
    __shared__ int s_carry;
    const int t = threadIdx.x, lane = t & 31, wid = t >> 5;
    if (t == 0) s_carry = 0;
    __syncthreads();
    for (int base = 0; base < Nn; base += 4096) {
        int i0 = base + t * 4;
        int v[4];
#pragma unroll
        for (int j = 0; j < 4; j++) v[j] = (i0 + j < Nn) ? g_deg[i0 + j] : 0;
        int tsum = v[0] + v[1] + v[2] + v[3];
        int x = tsum;
#pragma unroll
        for (int o = 1; o < 32; o <<= 1) {
            int y = __shfl_up_sync(0xffffffffu, x, o);
            if (lane >= o) x += y;
        }
        if (lane == 31) warpsum[wid] = x;
        __syncthreads();
        if (wid == 0) {
            int wv = warpsum[lane];
            int xx = wv;
#pragma unroll
            for (int o = 1; o < 32; o <<= 1) {
                int y = __shfl_up_sync(0xffffffffu, xx, o);
                if (lane >= o) xx += y;
            }
            warpsum[lane] = xx - wv;
        }
        __syncthreads();
        int run = s_carry + warpsum[wid] + (x - tsum);
#pragma unroll
        for (int j = 0; j < 4; j++) {
            if (i0 + j < Nn) { g_rowstart[i0 + j] = run; g_pos[i0 + j] = run; }
            run += v[j];
        }
        __syncthreads();
        if (t == 1023) s_carry = run;
        __syncthreads();
    }
    if (t == 0) g_rowstart[Nn] = s_carry;
}
__global__ void fill_kernel(const int* __restrict__ esrc,
                            const int* __restrict__ etrg, int E)
{
    int e = blockIdx.x * blockDim.x + threadIdx.x;
    if (e < E) {
        int tnode = etrg[e];
        int p = atomicAdd(&g_pos[tnode], 1);
        g_csr[p] = esrc[e];
    }
}

// ---------------- aggregation: single pass, owner-computed weights ----------
// proj gathered as fp16 (half the L2 bytes of fp32).
__global__ void agg_kernel(const float* __restrict__ bias,
                           float* __restrict__ out, int Nn)
{
    int w    = (blockIdx.x * blockDim.x + threadIdx.x) >> 5;
    int lane = threadIdx.x & 31;
    if (w >= Nn) return;
    const int h = lane >> 3, q = lane & 7;
    const int hb = h << 3;

    const int s0 = g_rowstart[w];
    const int s1 = g_rowstart[w + 1];
    const float strg = g_strg[w * NH + h];

    float denom = 0.f;
    float a0 = 0.f, a1 = 0.f, a2 = 0.f, a3 = 0.f, a4 = 0.f, a5 = 0.f, a6 = 0.f, a7 = 0.f;

    int i = s0;
    for (; i + 8 <= s1; i += 8) {
        int   sq = g_csr[i + q];
        float e  = g_ssrc[sq * NH + h] + strg;
        e = (e > 0.f) ? e : NEG * e;
        float wq = __expf(e);
        denom += wq;
#pragma unroll
        for (int j = 0; j < 8; j++) {
            float wgt = __shfl_sync(0xffffffffu, wq, hb + j);
            int   s   = __shfl_sync(0xffffffffu, sq, j);
            __half2 ph[4];
            *(uint4*)ph = *(const uint4*)&g_proj[(size_t)s * HF + lane * 8];
            float2 v0 = __half22float2(ph[0]);
            float2 v1 = __half22float2(ph[1]);
            float2 v2 = __half22float2(ph[2]);
            float2 v3 = __half22float2(ph[3]);
            a0 += wgt * v0.x; a1 += wgt * v0.y; a2 += wgt * v1.x; a3 += wgt * v1.y;
            a4 += wgt * v2.x; a5 += wgt * v2.y; a6 += wgt * v3.x; a7 += wgt * v3.y;
        }
    }
    if (i < s1) {
        int nb = s1 - i;
        float wq = 0.f;
        int   sq = 0;
        if (q < nb) {
            sq = g_csr[i + q];
            float e = g_ssrc[sq * NH + h] + strg;
            e = (e > 0.f) ? e : NEG * e;
            wq = __expf(e);
        }
        denom += wq;
        for (int j = 0; j < nb; j++) {
            float wgt = __shfl_sync(0xffffffffu, wq, hb + j);
            int   s   = __shfl_sync(0xffffffffu, sq, j);
            __half2 ph[4];
            *(uint4*)ph = *(const uint4*)&g_proj[(size_t)s * HF + lane * 8];
            float2 v0 = __half22float2(ph[0]);
            float2 v1 = __half22float2(ph[1]);
            float2 v2 = __half22float2(ph[2]);
            float2 v3 = __half22float2(ph[3]);
            a0 += wgt * v0.x; a1 += wgt * v0.y; a2 += wgt * v1.x; a3 += wgt * v1.y;
            a4 += wgt * v2.x; a5 += wgt * v2.y; a6 += wgt * v3.x; a7 += wgt * v3.y;
        }
    }

    denom += __shfl_xor_sync(0xffffffffu, denom, 4);
    denom += __shfl_xor_sync(0xffffffffu, denom, 2);
    denom += __shfl_xor_sync(0xffffffffu, denom, 1);
    const float inv = 1.f / (denom + 1e-16f);

    const size_t off = (size_t)w * HF + lane * 8;
    float4 k0 = *(const float4*)&g_skipb[off];
    float4 k1 = *(const float4*)&g_skipb[off + 4];
    float4 b0 = *(const float4*)&bias[lane * 8];
    float4 b1 = *(const float4*)&bias[lane * 8 + 4];
    float o0 = a0 * inv + k0.x + b0.x, o1 = a1 * inv + k0.y + b0.y;
    float o2 = a2 * inv + k0.z + b0.z, o3 = a3 * inv + k0.w + b0.w;
    float o4 = a4 * inv + k1.x + b1.x, o5 = a5 * inv + k1.y + b1.y;
    float o6 = a6 * inv + k1.z + b1.z, o7 = a7 * inv + k1.w + b1.w;
    o0 = (o0 > 0.f) ? o0 : NEG * o0;  o1 = (o1 > 0.f) ? o1 : NEG * o1;
    o2 = (o2 > 0.f) ? o2 : NEG * o2;  o3 = (o3 > 0.f) ? o3 : NEG * o3;
    o4 = (o4 > 0.f) ? o4 : NEG * o4;  o5 = (o5 > 0.f) ? o5 : NEG * o5;
    o6 = (o6 > 0.f) ? o6 : NEG * o6;  o7 = (o7 > 0.f) ? o7 : NEG * o7;
    *(float4*)&out[off]     = make_float4(o0, o1, o2, o3);
    *(float4*)&out[off + 4] = make_float4(o4, o5, o6, o7);
}

// ---------------- launch ----------------------------------------------------
extern "C" void kernel_launch(void* const* d_in, const int* in_sizes, int n_in,
                              void* d_out, int out_size)
{
    const float* x      = (const float*)d_in[0];
    const float* W      = (const float*)d_in[1];
    const float* a_src  = (const float*)d_in[2];
    const float* a_trg  = (const float*)d_in[3];
    const float* skip_w = (const float*)d_in[4];
    const float* bias   = (const float*)d_in[5];
    const int*   esrc   = (const int*)d_in[6];
    const int*   etrg   = (const int*)d_in[7];
    float* out = (float*)d_out;

    const int Nn = in_sizes[0] / HF;   // 50000
    const int E  = in_sizes[6];        // 800000

    cudaFuncSetAttribute(gemm_kernel, cudaFuncAttributeMaxDynamicSharedMemorySize, GEMM_SMEM);

    // fork-join: CSR chain (hist/scan/fill) overlaps the GEMM on a side stream
    cudaStream_t s_side;
    cudaEvent_t ev_fork, ev_join;
    cudaStreamCreateWithFlags(&s_side, cudaStreamNonBlocking);
    cudaEventCreateWithFlags(&ev_fork, cudaEventDisableTiming);
    cudaEventCreateWithFlags(&ev_join, cudaEventDisableTiming);

    prep_bt_kernel<<<(512 * 256 + 255) / 256, 256>>>(W, skip_w, Nn);   // zeroes g_deg

    cudaEventRecord(ev_fork, 0);
    cudaStreamWaitEvent(s_side, ev_fork, 0);
    hist_kernel<<<(E + 255) / 256, 256, 0, s_side>>>(etrg, E);
    scan_kernel<<<1, 1024, 0, s_side>>>(Nn);
    fill_kernel<<<(E + 255) / 256, 256, 0, s_side>>>(esrc, etrg, E);
    cudaEventRecord(ev_join, s_side);

    gemm_kernel<<<(Nn + 63) / 64, 256, GEMM_SMEM>>>(x, a_src, a_trg, Nn);

    cudaStreamWaitEvent(0, ev_join, 0);
    int nblk = (Nn * 32 + 255) / 256;
    agg_kernel<<<nblk, 256>>>(bias, out, Nn);

    cudaEventDestroy(ev_fork);
    cudaEventDestroy(ev_join);
    cudaStreamDestroy(s_side);
}

// round 14
// speedup vs baseline: 1.2026x; 1.2026x over previous
#include <cuda_runtime.h>
#include <cuda_fp16.h>
#include <cstdint>

#define MAX_N 50000
#define MAX_E 800000
#define HF    256
#define NH    4
#define NF    64
#define NEG   0.2f

// ---------------- scratch (device globals; no allocations allowed) ----------
__device__ float  g_proj [(size_t)MAX_N * HF];
__device__ float  g_skipb[(size_t)MAX_N * HF];
__device__ float  g_ssrc [MAX_N * NH];
__device__ float  g_strg [MAX_N * NH];
__device__ int    g_deg  [MAX_N];
__device__ int    g_rowstart[MAX_N + 1];
__device__ int    g_pos  [MAX_N];
__device__ int    g_csr  [MAX_E];
__device__ __half g_bt[512 * 256];   // [n 0..511][k] = (W | skip_w)^T, fp16

// ---------------- PTX helpers (arch-generic: sm_80-era) ----------------------
__device__ __forceinline__ uint32_t smem_u32(const void* p) {
    uint32_t a;
    asm("{ .reg .u64 t; cvta.to.shared.u64 t, %1; cvt.u32.u64 %0, t; }" : "=r"(a) : "l"(p));
    return a;
}
__device__ __forceinline__ void cp16(uint32_t saddr, const void* g, int srcsize) {
    asm volatile("cp.async.cg.shared.global [%0], [%1], 16, %2;"
                 :: "r"(saddr), "l"(g), "r"(srcsize) : "memory");
}
#define CP_COMMIT() asm volatile("cp.async.commit_group;" ::: "memory")

#define LDSM_X4(d0, d1, d2, d3, addr) \
    asm volatile("ldmatrix.sync.aligned.m8n8.x4.shared.b16 {%0,%1,%2,%3}, [%4];" \
                 : "=r"(d0), "=r"(d1), "=r"(d2), "=r"(d3) : "r"(addr))

__device__ __forceinline__ void mma16816(float* c, const uint32_t* a, const uint32_t* b) {
    asm volatile(
        "mma.sync.aligned.m16n8k16.row.col.f32.f16.f16.f32 "
        "{%0,%1,%2,%3}, {%4,%5,%6,%7}, {%8,%9}, {%0,%1,%2,%3};"
        : "+f"(c[0]), "+f"(c[1]), "+f"(c[2]), "+f"(c[3])
        : "r"(a[0]), "r"(a[1]), "r"(a[2]), "r"(a[3]), "r"(b[0]), "r"(b[1]));
}

// ---------------- weight prep (also zeroes g_deg) -----------------------------
__global__ void prep_bt_kernel(const float* __restrict__ W, const float* __restrict__ skw,
                               int Nn) {
    int i = blockIdx.x * blockDim.x + threadIdx.x;
    if (i < Nn) g_deg[i] = 0;
    if (i < 512 * 256) {
        int n = i >> 8, k = i & 255;
        float v = (n < 256) ? W[k * 256 + n] : skw[k * 256 + (n - 256)];
        g_bt[i] = __float2half_rn(v);
    }
}

// ---------------- HMMA GEMM: C[M,512] = A[M,256] @ BT^T ----------------------
// Pure fp16 x fp16, fp32 accum (element err ~2^-11 each side, global ~3e-4).
// 128-row CTA tiles, A resident fp16 (67.6 KB) -> 2 CTAs/SM (102 KB total).
// 8 warps (2m x 4n), warp tile 64x32; 3-stage cp.async B pipeline.
// Attention scores fused into the bn 0/1 epilogues via smem accumulation.
#define AP       264      // padded A row stride (elements)
#define SA_OFF   0
#define SB_BASE  67584
#define SB_STAGE 10240
#define LDB_PAD  40
#define SC_OFF   98304    // 128 rows x 4 heads x 2 = 1024 floats
#define GEMM_SMEM (98304 + 4096)   // 102400

__device__ __forceinline__ void load_A_convert(char* smem, const float* __restrict__ x,
                                               int bm, int M, int tid) {
#pragma unroll
    for (int it = 0; it < 16; it++) {
        int id = tid + it * 256;          // 0..4095 : 128 rows x 32 chunks(8 floats)
        int r = id >> 5, c = id & 31;
        int gr = bm * 128 + r;
        float4 v0 = make_float4(0.f, 0.f, 0.f, 0.f), v1 = v0;
        if (gr < M) {
            const float* src = x + (size_t)gr * 256 + c * 8;
            v0 = *(const float4*)src;
            v1 = *(const float4*)(src + 4);
        }
        __half2 hi2[4];
        hi2[0] = __floats2half2_rn(v0.x, v0.y);
        hi2[1] = __floats2half2_rn(v0.z, v0.w);
        hi2[2] = __floats2half2_rn(v1.x, v1.y);
        hi2[3] = __floats2half2_rn(v1.z, v1.w);
        uint32_t dst = (uint32_t)(r * AP * 2 + c * 16);
        *(uint4*)(smem + SA_OFF + dst) = *(uint4*)hi2;
    }
}
__device__ __forceinline__ void issue_B(uint32_t sb, int g, int tid) {
    int bn = g >> 3, ks = g & 7;
    uint32_t base = sb + SB_BASE + (uint32_t)(g % 3) * SB_STAGE;
    int row = tid >> 1;
#pragma unroll
    for (int j = 0; j < 2; j++) {
        int chunk = (tid & 1) * 2 + j;               // 0..3
        int gcol  = ks * 32 + chunk * 8;
        int gn    = bn * 128 + row;
        uint32_t dst = (uint32_t)(row * LDB_PAD * 2 + chunk * 16);
        cp16(base + dst, &g_bt[(size_t)gn * 256 + gcol], 16);
    }
}

__global__ __launch_bounds__(256, 2) void gemm_kernel(const float* __restrict__ x,
                                                      const float* __restrict__ a_src,
                                                      const float* __restrict__ a_trg,
                                                      int M)
{
    extern __shared__ __align__(16) char smem[];
    const uint32_t sb = smem_u32(smem);
    float* s_sc = (float*)(smem + SC_OFF);
    const int tid  = threadIdx.x;
    const int wid  = tid >> 5;
    const int lane = tid & 31;
    const int bm   = blockIdx.x;

    const int wm = (wid >> 2) * 64;   // warp m offset (0 / 64)
    const int wn = (wid & 3) * 32;    // warp n offset (0/32/64/96)

    float acc[4][4][4];
#pragma unroll
    for (int i = 0; i < 4; i++)
#pragma unroll
        for (int j = 0; j < 4; j++)
#pragma unroll
            for (int q = 0; q < 4; q++) acc[i][j][q] = 0.f;

    const int g8 = lane >> 3;    // ldmatrix address group 0..3
    const int r8 = lane & 7;

    issue_B(sb, 0, tid);
    CP_COMMIT();
    issue_B(sb, 1, tid);
    CP_COMMIT();
    load_A_convert(smem, x, bm, M, tid);
    for (int v = tid; v < 1024; v += 256) s_sc[v] = 0.f;

#pragma unroll 1
    for (int g = 0; g < 32; g++) {
        if (g + 2 < 32) {
            issue_B(sb, g + 2, tid);
            CP_COMMIT();
            asm volatile("cp.async.wait_group 2;" ::: "memory");
        } else if (g + 1 < 32) {
            asm volatile("cp.async.wait_group 1;" ::: "memory");
        } else {
            asm volatile("cp.async.wait_group 0;" ::: "memory");
        }
        __syncthreads();

        const int bn = g >> 3, ks = g & 7;
        const uint32_t stB = sb + SB_BASE + (uint32_t)(g % 3) * SB_STAGE;
#pragma unroll
        for (int k16 = 0; k16 < 32; k16 += 16) {
            uint32_t ah[4][4], bh[4][2];
            {
                int arow = wm + (g8 & 1) * 8 + r8;
                int acol = ks * 32 + k16 + (g8 >> 1) * 8;
                uint32_t aoff = (uint32_t)(arow * AP + acol) * 2;
#pragma unroll
                for (int mi = 0; mi < 4; mi++) {
                    uint32_t ad = sb + SA_OFF + aoff + (uint32_t)(mi * 16 * AP * 2);
                    LDSM_X4(ah[mi][0], ah[mi][1], ah[mi][2], ah[mi][3], ad);
                }
            }
            {
                int brow = wn + (g8 >> 1) * 8 + r8;
                int bcol = k16 + (g8 & 1) * 8;
                uint32_t boff = (uint32_t)(brow * LDB_PAD + bcol) * 2;
#pragma unroll
                for (int j = 0; j < 2; j++) {
                    uint32_t bd = stB + boff + (uint32_t)(j * 16 * LDB_PAD * 2);
                    LDSM_X4(bh[2 * j][0], bh[2 * j][1], bh[2 * j + 1][0], bh[2 * j + 1][1],
                            bd);
                }
            }
#pragma unroll
            for (int mi = 0; mi < 4; mi++)
#pragma unroll
                for (int ni = 0; ni < 4; ni++)
                    mma16816(acc[mi][ni], ah[mi], bh[ni]);
        }
        __syncthreads();

        if (ks == 7) {
            float* dst = (bn < 2) ? g_proj : g_skipb;
            const int colbase = (bn & 1) * 128 + wn;

            if (bn < 2) {
                const int h = colbase >> 6;     // all 8 cols of a thread share a head
#pragma unroll
                for (int mi = 0; mi < 4; mi++) {
                    int rl = wm + mi * 16 + (lane >> 2);
                    float s0 = 0.f, t0 = 0.f, s1 = 0.f, t1 = 0.f;
#pragma unroll
                    for (int ni = 0; ni < 4; ni++) {
                        int gc = colbase + ni * 8 + (lane & 3) * 2;
                        float as0 = a_src[gc], as1 = a_src[gc + 1];
                        float at0 = a_trg[gc], at1 = a_trg[gc + 1];
                        s0 += acc[mi][ni][0] * as0 + acc[mi][ni][1] * as1;
                        t0 += acc[mi][ni][0] * at0 + acc[mi][ni][1] * at1;
                        s1 += acc[mi][ni][2] * as0 + acc[mi][ni][3] * as1;
                        t1 += acc[mi][ni][2] * at0 + acc[mi][ni][3] * at1;
                    }
                    atomicAdd(&s_sc[rl * 8 + h * 2 + 0], s0);
                    atomicAdd(&s_sc[rl * 8 + h * 2 + 1], t0);
                    atomicAdd(&s_sc[(rl + 8) * 8 + h * 2 + 0], s1);
                    atomicAdd(&s_sc[(rl + 8) * 8 + h * 2 + 1], t1);
                }
            }

#pragma unroll
            for (int mi = 0; mi < 4; mi++) {
                int gr = bm * 128 + wm + mi * 16 + (lane >> 2);
#pragma unroll
                for (int ni = 0; ni < 4; ni++) {
                    int gc = colbase + ni * 8 + (lane & 3) * 2;
                    if (gr < M)
                        *(float2*)&dst[(size_t)gr * 256 + gc] =
                            make_float2(acc[mi][ni][0], acc[mi][ni][1]);
                    if (gr + 8 < M)
                        *(float2*)&dst[(size_t)(gr + 8) * 256 + gc] =
                            make_float2(acc[mi][ni][2], acc[mi][ni][3]);
                    acc[mi][ni][0] = acc[mi][ni][1] = acc[mi][ni][2] = acc[mi][ni][3] = 0.f;
                }
            }

            if (bn == 1) {
                __syncthreads();                 // all score atomics done
                for (int v = tid; v < 512; v += 256) {
                    int r = v >> 2, hh = v & 3;
                    int gr2 = bm * 128 + r;
                    if (gr2 < M) {
                        g_ssrc[gr2 * NH + hh] = s_sc[r * 8 + hh * 2];
                        g_strg[gr2 * NH + hh] = s_sc[r * 8 + hh * 2 + 1];
                    }
                }
            }
        }
    }
}

// ---------------- CSR construction ------------------------------------------
__global__ void hist_kernel(const int* __restrict__ etrg, int E)
{
    int e = blockIdx.x * blockDim.x + threadIdx.x;
    if (e < E) atomicAdd(&g_deg[etrg[e]], 1);
}
__global__ void scan_kernel(int Nn)
{
    __shared__ int warpsum[32];
    __shared__ int s_carry;
    const int t = threadIdx.x, lane = t & 31, wid = t >> 5;
    if (t == 0) s_carry = 0;
    __syncthreads();
    for (int base = 0; base < Nn; base += 4096) {
        int i0 = base + t * 4;
        int v[4];
#pragma unroll
        for (int j = 0; j < 4; j++) v[j] = (i0 + j < Nn) ? g_deg[i0 + j] : 0;
        int tsum = v[0] + v[1] + v[2] + v[3];
        int x = tsum;
#pragma unroll
        for (int o = 1; o < 32; o <<= 1) {
            int y = __shfl_up_sync(0xffffffffu, x, o);
            if (lane >= o) x += y;
        }
        if (lane == 31) warpsum[wid] = x;
        __syncthreads();
        if (wid == 0) {
            int wv = warpsum[lane];
            int xx = wv;
#pragma unroll
            for (int o = 1; o < 32; o <<= 1) {
                int y = __shfl_up_sync(0xffffffffu, xx, o);
                if (lane >= o) xx += y;
            }
            warpsum[lane] = xx - wv;
        }
        __syncthreads();
        int run = s_carry + warpsum[wid] + (x - tsum);
#pragma unroll
        for (int j = 0; j < 4; j++) {
            if (i0 + j < Nn) { g_rowstart[i0 + j] = run; g_pos[i0 + j] = run; }
            run += v[j];
        }
        __syncthreads();
        if (t == 1023) s_carry = run;
        __syncthreads();
    }
    if (t == 0) g_rowstart[Nn] = s_carry;
}
__global__ void fill_kernel(const int* __restrict__ esrc,
                            const int* __restrict__ etrg, int E)
{
    int e = blockIdx.x * blockDim.x + threadIdx.x;
    if (e < E) {
        int tnode = etrg[e];
        int p = atomicAdd(&g_pos[tnode], 1);
        g_csr[p] = esrc[e];
    }
}

// ---------------- aggregation: single pass, owner-computed weights ----------
__global__ void agg_kernel(const float* __restrict__ bias,
                           float* __restrict__ out, int Nn)
{
    int w    = (blockIdx.x * blockDim.x + threadIdx.x) >> 5;
    int lane = threadIdx.x & 31;
    if (w >= Nn) return;
    const int h = lane >> 3, q = lane & 7;
    const int hb = h << 3;

    const int s0 = g_rowstart[w];
    const int s1 = g_rowstart[w + 1];
    const float strg = g_strg[w * NH + h];

    float denom = 0.f;
    float a0 = 0.f, a1 = 0.f, a2 = 0.f, a3 = 0.f, a4 = 0.f, a5 = 0.f, a6 = 0.f, a7 = 0.f;

    int i = s0;
    for (; i + 8 <= s1; i += 8) {
        int   sq = g_csr[i + q];
        float e  = g_ssrc[sq * NH + h] + strg;
        e = (e > 0.f) ? e : NEG * e;
        float wq = __expf(e);
        denom += wq;
#pragma unroll
        for (int j = 0; j < 8; j++) {
            float wgt = __shfl_sync(0xffffffffu, wq, hb + j);
            int   s   = __shfl_sync(0xffffffffu, sq, j);
            const float* pr = g_proj + (size_t)s * HF + lane * 8;
            float4 p0 = *(const float4*)pr;
            float4 p1 = *(const float4*)(pr + 4);
            a0 += wgt * p0.x; a1 += wgt * p0.y; a2 += wgt * p0.z; a3 += wgt * p0.w;
            a4 += wgt * p1.x; a5 += wgt * p1.y; a6 += wgt * p1.z; a7 += wgt * p1.w;
        }
    }
    if (i < s1) {
        int nb = s1 - i;
        float wq = 0.f;
        int   sq = 0;
        if (q < nb) {
            sq = g_csr[i + q];
            float e = g_ssrc[sq * NH + h] + strg;
            e = (e > 0.f) ? e : NEG * e;
            wq = __expf(e);
        }
        denom += wq;
        for (int j = 0; j < nb; j++) {
            float wgt = __shfl_sync(0xffffffffu, wq, hb + j);
            int   s   = __shfl_sync(0xffffffffu, sq, j);
            const float* pr = g_proj + (size_t)s * HF + lane * 8;
            float4 p0 = *(const float4*)pr;
            float4 p1 = *(const float4*)(pr + 4);
            a0 += wgt * p0.x; a1 += wgt * p0.y; a2 += wgt * p0.z; a3 += wgt * p0.w;
            a4 += wgt * p1.x; a5 += wgt * p1.y; a6 += wgt * p1.z; a7 += wgt * p1.w;
        }
    }

    denom += __shfl_xor_sync(0xffffffffu, denom, 4);
    denom += __shfl_xor_sync(0xffffffffu, denom, 2);
    denom += __shfl_xor_sync(0xffffffffu, denom, 1);
    const float inv = 1.f / (denom + 1e-16f);

    const size_t off = (size_t)w * HF + lane * 8;
    float4 k0 = *(const float4*)&g_skipb[off];
    float4 k1 = *(const float4*)&g_skipb[off + 4];
    float4 b0 = *(const float4*)&bias[lane * 8];
    float4 b1 = *(const float4*)&bias[lane * 8 + 4];
    float o0 = a0 * inv + k0.x + b0.x, o1 = a1 * inv + k0.y + b0.y;
    float o2 = a2 * inv + k0.z + b0.z, o3 = a3 * inv + k0.w + b0.w;
    float o4 = a4 * inv + k1.x + b1.x, o5 = a5 * inv + k1.y + b1.y;
    float o6 = a6 * inv + k1.z + b1.z, o7 = a7 * inv + k1.w + b1.w;
    o0 = (o0 > 0.f) ? o0 : NEG * o0;  o1 = (o1 > 0.f) ? o1 : NEG * o1;
    o2 = (o2 > 0.f) ? o2 : NEG * o2;  o3 = (o3 > 0.f) ? o3 : NEG * o3;
    o4 = (o4 > 0.f) ? o4 : NEG * o4;  o5 = (o5 > 0.f) ? o5 : NEG * o5;
    o6 = (o6 > 0.f) ? o6 : NEG * o6;  o7 = (o7 > 0.f) ? o7 : NEG * o7;
    *(float4*)&out[off]     = make_float4(o0, o1, o2, o3);
    *(float4*)&out[off + 4] = make_float4(o4, o5, o6, o7);
}

// ---------------- launch ----------------------------------------------------
extern "C" void kernel_launch(void* const* d_in, const int* in_sizes, int n_in,
                              void* d_out, int out_size)
{
    const float* x      = (const float*)d_in[0];
    const float* W      = (const float*)d_in[1];
    const float* a_src  = (const float*)d_in[2];
    const float* a_trg  = (const float*)d_in[3];
    const float* skip_w = (const float*)d_in[4];
    const float* bias   = (const float*)d_in[5];
    const int*   esrc   = (const int*)d_in[6];
    const int*   etrg   = (const int*)d_in[7];
    float* out = (float*)d_out;

    const int Nn = in_sizes[0] / HF;   // 50000
    const int E  = in_sizes[6];        // 800000

    cudaFuncSetAttribute(gemm_kernel, cudaFuncAttributeMaxDynamicSharedMemorySize, GEMM_SMEM);

    // fork-join: CSR chain (hist/scan/fill) overlaps the GEMM on a side stream
    cudaStream_t s_side;
    cudaEvent_t ev_fork, ev_join;
    cudaStreamCreateWithFlags(&s_side, cudaStreamNonBlocking);
    cudaEventCreateWithFlags(&ev_fork, cudaEventDisableTiming);
    cudaEventCreateWithFlags(&ev_join, cudaEventDisableTiming);

    prep_bt_kernel<<<(512 * 256 + 255) / 256, 256>>>(W, skip_w, Nn);   // zeroes g_deg

    cudaEventRecord(ev_fork, 0);
    cudaStreamWaitEvent(s_side, ev_fork, 0);
    hist_kernel<<<(E + 255) / 256, 256, 0, s_side>>>(etrg, E);
    scan_kernel<<<1, 1024, 0, s_side>>>(Nn);
    fill_kernel<<<(E + 255) / 256, 256, 0, s_side>>>(esrc, etrg, E);
    cudaEventRecord(ev_join, s_side);

    gemm_kernel<<<(Nn + 127) / 128, 256, GEMM_SMEM>>>(x, a_src, a_trg, Nn);

    cudaStreamWaitEvent(0, ev_join, 0);
    int nblk = (Nn * 32 + 255) / 256;
    agg_kernel<<<nblk, 256>>>(bias, out, Nn);

    cudaEventDestroy(ev_fork);
    cudaEventDestroy(ev_join);
    cudaStreamDestroy(s_side);
}